// round 12
// baseline (speedup 1.0000x reference)
#include <cuda_runtime.h>
#include <cuda_bf16.h>
#include <math.h>

#define Bz 2
#define Sz 2048
#define Dm 1024
#define Hh 16
#define HD 64
#define NT (Bz*Sz)          // 4096 tokens

// ---------------- scratch (device globals) ----------------
__device__ float g_featA[NT * 512];
__device__ float g_featF[NT * 1024];
__device__ float g_hidden[NT * 1024];
__device__ float g_q[NT * 1024];
__device__ float g_k[NT * 1024];
__device__ float g_v[NT * 1024];
__device__ float g_attn[NT * 1024];
__device__ float g_bias[Bz * Sz * Sz];     // 33.5 MB
__device__ float g_zero_bias[1024];        // stays zero

// ---------------- tf32 rounding ----------------
__device__ __forceinline__ float tf32r(float x) {
    unsigned r;
    asm("cvt.rna.tf32.f32 %0, %1;" : "=r"(r) : "f"(x));
    return __uint_as_float(r);
}

// ---------------- mma helper ----------------
__device__ __forceinline__ void mma_tf32(float* acc, const unsigned* a, unsigned b0, unsigned b1) {
    asm volatile(
        "mma.sync.aligned.m16n8k8.row.col.f32.tf32.tf32.f32 "
        "{%0,%1,%2,%3}, {%4,%5,%6,%7}, {%8,%9}, {%0,%1,%2,%3};"
        : "+f"(acc[0]), "+f"(acc[1]), "+f"(acc[2]), "+f"(acc[3])
        : "r"(a[0]), "r"(a[1]), "r"(a[2]), "r"(a[3]), "r"(b0), "r"(b1));
}

// ---------------- featurize ----------------
__global__ void featurize_kernel(const int* __restrict__ enc,
                                 const float* __restrict__ emb1_w, const float* __restrict__ emb1_b,
                                 const float* __restrict__ log_w,  const float* __restrict__ log_b,
                                 const float* __restrict__ prime_w,const float* __restrict__ prime_b,
                                 const float* __restrict__ div_w,  const float* __restrict__ div_b,
                                 const float* __restrict__ bit_w,  const float* __restrict__ bit_b,
                                 float* __restrict__ featA, float* __restrict__ featF)
{
    int t = blockIdx.x;
    int tid = threadIdx.x;
    int e = enc[t];
    float ef = (float)e;
    float norm = ef / 2147483647.0f;
    float lg = logf(ef + 1.0f);

    __shared__ float pflag[10];
    __shared__ float dfrac[20];
    __shared__ float bflag[32];
    if (tid < 10) {
        const int primes[10] = {2,3,5,7,11,13,17,19,23,29};
        pflag[tid] = (e % primes[tid] == 0) ? 1.0f : 0.0f;
    } else if (tid < 30) {
        int tv = (tid - 10) + 2;
        dfrac[tid-10] = (float)(e % tv) / (float)tv;
    } else if (tid < 62) {
        int s = tid - 30;
        bflag[s] = (float)((e >> s) & 1);
    }
    __syncthreads();

    for (int c = tid; c < 512; c += 256) {
        float vv = fmaf(norm, emb1_w[c], emb1_b[c]);
        featA[t*512 + c] = tf32r(fmaxf(vv, 0.0f));
    }
    for (int c = tid; c < 1024; c += 256) {
        int cc = c & 255;
        float vv;
        if (c < 256) {
            vv = fmaf(lg, log_w[cc], log_b[cc]);
        } else if (c < 512) {
            vv = prime_b[cc];
            #pragma unroll
            for (int p = 0; p < 10; p++) vv = fmaf(pflag[p], prime_w[p*256 + cc], vv);
        } else if (c < 768) {
            vv = div_b[cc];
            #pragma unroll
            for (int p = 0; p < 20; p++) vv = fmaf(dfrac[p], div_w[p*256 + cc], vv);
        } else {
            vv = bit_b[cc];
            #pragma unroll
            for (int p = 0; p < 32; p++) vv = fmaf(bflag[p], bit_w[p*256 + cc], vv);
        }
        featF[t*1024 + c] = tf32r(vv);
    }
}

// ---------------- pairwise gcd-approx bias ----------------
// encodings in [1, 1e6) < 2^20: exact in fp32 -> fast float-division modulo
// with 2-step correction (exact for these ranges).
__device__ __forceinline__ int fastmod(int a, int m) {
    int q = __float2int_rz(__fdividef(__int2float_rn(a), __int2float_rn(m)));
    int r = a - q * m;
    r += (r >> 31) & m;          // r < 0  -> += m
    if (r >= m) r -= m;          // r >= m -> -= m
    return r;
}

__global__ void bias_kernel(const int* __restrict__ enc, float* __restrict__ biasOut, int b)
{
    int idx = blockIdx.x * blockDim.x + threadIdx.x;   // over Sz*Sz
    int j = idx & (Sz - 1);
    int i = idx >> 11;
    int ei = enc[b*Sz + i];
    int ej = enc[b*Sz + j];
    float bias;
    if (i == j) {
        bias = 0.0f;
    } else {
        int m1 = fastmod(ei, ej + 1);
        int m2 = fastmod(ej, ei + 1);
        int g  = m1 < m2 ? m1 : m2;
        int mx = ei > ej ? ei : ej;
        bias = __fdividef(__int2float_rn(g), __int2float_rn(mx + 1));
    }
    biasOut[(size_t)b * Sz * Sz + idx] = bias;
}

// ---------------- tf32 mma GEMM: 128x128 block tile, 32 k-tile, 8 warps ----------------
// A operands (activations) are pre-rounded to tf32 by producers.
// B operands (weights) are raw fp32; fragments are rounded with cvt.rna after LDS.
#define BK 32
#define APAD 36
#define BPAD 132
#define AS_STAGE (128*APAD)
#define BS_STAGE (BK*BPAD)
#define GSMEM ((2*AS_STAGE + 2*BS_STAGE)*4)

__device__ __forceinline__ void cp16(float* dst, const float* src) {
    unsigned a = (unsigned)__cvta_generic_to_shared(dst);
    asm volatile("cp.async.cg.shared.global [%0], [%1], 16;\n" :: "r"(a), "l"(src));
}

__device__ __forceinline__ void load_stage(const float* __restrict__ A,
                                           const float* __restrict__ B, int K,
                                           int br, int bc, int k0,
                                           float* As, float* Bs, int tid)
{
    #pragma unroll
    for (int i = 0; i < 4; i++) {
        int f = tid + i*256;
        int r = f >> 3, c = (f & 7) << 2;
        cp16(&As[r*APAD + c], A + (size_t)(br + r)*K + k0 + c);
    }
    #pragma unroll
    for (int i = 0; i < 4; i++) {
        int f = tid + i*256;
        int r = f >> 5, c = (f & 31) << 2;
        cp16(&Bs[r*BPAD + c], B + (size_t)(k0 + r)*1024 + bc + c);
    }
    asm volatile("cp.async.commit_group;\n");
}

__device__ __forceinline__ void compute_stage(const float* __restrict__ As,
                                              const float* __restrict__ Bs,
                                              int warpM, int warpN, int lane,
                                              float acc[4][4][4])
{
    int lr = lane >> 2, lc = lane & 3;
    #pragma unroll
    for (int k8 = 0; k8 < BK; k8 += 8) {
        unsigned a[4][4], b[4][2];
        #pragma unroll
        for (int mt = 0; mt < 4; mt++) {
            const float* p = &As[(warpM*64 + mt*16 + lr)*APAD + k8 + lc];
            a[mt][0] = __float_as_uint(p[0]);
            a[mt][1] = __float_as_uint(p[8*APAD]);
            a[mt][2] = __float_as_uint(p[4]);
            a[mt][3] = __float_as_uint(p[8*APAD + 4]);
        }
        #pragma unroll
        for (int nt = 0; nt < 4; nt++) {
            const float* p = &Bs[(k8 + lc)*BPAD + warpN*32 + nt*8 + lr];
            b[nt][0] = __float_as_uint(tf32r(p[0]));
            b[nt][1] = __float_as_uint(tf32r(p[4*BPAD]));
        }
        #pragma unroll
        for (int mt = 0; mt < 4; mt++)
            #pragma unroll
            for (int nt = 0; nt < 4; nt++)
                mma_tf32(acc[mt][nt], a[mt], b[nt][0], b[nt][1]);
    }
}

__device__ __forceinline__ void mma_gemm(const float* __restrict__ A,
                                         const float* __restrict__ B, int K,
                                         int br, int bc, int tid, float* sm,
                                         float acc[4][4][4])
{
    float* As0 = sm;
    float* As1 = sm + AS_STAGE;
    float* Bs0 = sm + 2*AS_STAGE;
    float* Bs1 = sm + 2*AS_STAGE + BS_STAGE;
    int warp = tid >> 5, lane = tid & 31;
    int warpM = warp >> 2, warpN = warp & 3;
    int KT = K / BK;
    load_stage(A, B, K, br, bc, 0, As0, Bs0, tid);
    for (int kt = 0; kt < KT; kt++) {
        float* Asc = (kt & 1) ? As1 : As0;
        float* Bsc = (kt & 1) ? Bs1 : Bs0;
        if (kt + 1 < KT) {
            float* Asn = ((kt+1) & 1) ? As1 : As0;
            float* Bsn = ((kt+1) & 1) ? Bs1 : Bs0;
            load_stage(A, B, K, br, bc, (kt+1)*BK, Asn, Bsn, tid);
            asm volatile("cp.async.wait_group 1;\n");
        } else {
            asm volatile("cp.async.wait_group 0;\n");
        }
        __syncthreads();
        compute_stage(Asc, Bsc, warpM, warpN, lane, acc);
        __syncthreads();
    }
}

__device__ __forceinline__ void mma_epi(float* __restrict__ C,
                                        const float* __restrict__ b1,
                                        const float* __restrict__ b2,
                                        int br, int bc, int tid,
                                        float acc[4][4][4], bool round_out)
{
    int warp = tid >> 5, lane = tid & 31;
    int warpM = warp >> 2, warpN = warp & 3;
    int lr = lane >> 2, lc = lane & 3;
    #pragma unroll
    for (int mt = 0; mt < 4; mt++)
        #pragma unroll
        for (int nt = 0; nt < 4; nt++) {
            int row = br + warpM*64 + mt*16 + lr;
            int col = bc + warpN*32 + nt*8 + lc*2;
            float bb0 = b1[col]   + b2[col];
            float bb1 = b1[col+1] + b2[col+1];
            float2 v0, v1;
            v0.x = acc[mt][nt][0] + bb0;
            v0.y = acc[mt][nt][1] + bb1;
            v1.x = acc[mt][nt][2] + bb0;
            v1.y = acc[mt][nt][3] + bb1;
            if (round_out) {
                v0.x = tf32r(v0.x); v0.y = tf32r(v0.y);
                v1.x = tf32r(v1.x); v1.y = tf32r(v1.y);
            }
            *(float2*)(C + (size_t)row*1024 + col) = v0;
            *(float2*)(C + (size_t)(row+8)*1024 + col) = v1;
        }
}

extern __shared__ float dsm[];

__global__ void __launch_bounds__(256) gemm_hidden_t(
        const float* __restrict__ A1, const float* __restrict__ B1,
        const float* __restrict__ A2, const float* __restrict__ B2,
        const float* __restrict__ bias1, const float* __restrict__ bias2,
        float* __restrict__ C)
{
    float acc[4][4][4];
    #pragma unroll
    for (int i = 0; i < 4; i++)
        #pragma unroll
        for (int j = 0; j < 4; j++)
            #pragma unroll
            for (int k = 0; k < 4; k++) acc[i][j][k] = 0.0f;
    int br = blockIdx.y * 128, bc = blockIdx.x * 128;
    mma_gemm(A1, B1, 512,  br, bc, threadIdx.x, dsm, acc);
    mma_gemm(A2, B2, 1024, br, bc, threadIdx.x, dsm, acc);
    mma_epi(C, bias1, bias2, br, bc, threadIdx.x, acc, true);
}

__global__ void __launch_bounds__(256) gemm_qkv_t(
        const float* __restrict__ Hd,
        const float* __restrict__ q_w, const float* __restrict__ q_b,
        const float* __restrict__ k_w, const float* __restrict__ k_b,
        const float* __restrict__ v_w, const float* __restrict__ v_b,
        const float* __restrict__ zero_b,
        float* __restrict__ Qo, float* __restrict__ Ko, float* __restrict__ Vo)
{
    const float* W; const float* bb; float* C;
    if (blockIdx.z == 0)      { W = q_w; bb = q_b; C = Qo; }
    else if (blockIdx.z == 1) { W = k_w; bb = k_b; C = Ko; }
    else                      { W = v_w; bb = v_b; C = Vo; }
    float acc[4][4][4];
    #pragma unroll
    for (int i = 0; i < 4; i++)
        #pragma unroll
        for (int j = 0; j < 4; j++)
            #pragma unroll
            for (int k = 0; k < 4; k++) acc[i][j][k] = 0.0f;
    int br = blockIdx.y * 128, bc = blockIdx.x * 128;
    mma_gemm(Hd, W, 1024, br, bc, threadIdx.x, dsm, acc);
    mma_epi(C, bb, zero_b, br, bc, threadIdx.x, acc, false);
}

__global__ void __launch_bounds__(256) gemm_single_t(
        const float* __restrict__ A, const float* __restrict__ W,
        const float* __restrict__ bias, const float* __restrict__ zero_b,
        float* __restrict__ C)
{
    float acc[4][4][4];
    #pragma unroll
    for (int i = 0; i < 4; i++)
        #pragma unroll
        for (int j = 0; j < 4; j++)
            #pragma unroll
            for (int k = 0; k < 4; k++) acc[i][j][k] = 0.0f;
    int br = blockIdx.y * 128, bc = blockIdx.x * 128;
    mma_gemm(A, W, 1024, br, bc, threadIdx.x, dsm, acc);
    mma_epi(C, bias, zero_b, br, bc, threadIdx.x, acc, false);
}

// ---------------- tensor-core flash attention ----------------
// 64 q-rows per block (4 warps x 16), 64-key tiles, tf32 mma.
// QK^T: 3-mma error-compensated split (~fp32 accurate scores).
// P@V: single-pass tf32.
#define KPAD 68
#define VPAD 72
#define PPAD 68
#define ATTN_SMEM ((2*64*KPAD + 64*VPAD + 64*PPAD)*4)

__global__ void __launch_bounds__(128) attention_mma_kernel(
        const float* __restrict__ q, const float* __restrict__ k, const float* __restrict__ v,
        const float* __restrict__ biasG, const float* __restrict__ gcd_w,
        float* __restrict__ o)
{
    extern __shared__ float sm[];
    float* sKb = sm;
    float* sKs = sm + 64*KPAD;
    float* sV  = sm + 2*64*KPAD;
    float* sP  = sm + 2*64*KPAD + 64*VPAD;

    int bh = blockIdx.y;
    int b = bh >> 4, h = bh & 15;
    int i0 = blockIdx.x * 64;
    int tid = threadIdx.x;
    int w = tid >> 5, lane = tid & 31;
    int lr = lane >> 2, lc = lane & 3;
    float gw = gcd_w[0];
    const float scale = 0.125f;                // 1/sqrt(64)
    const float* biasB = biasG + (size_t)b * Sz * Sz;

    // ---- Q fragments in registers (split big/small), loop-invariant ----
    unsigned Qb[8][4], Qs[8][4];
    {
        int r0 = i0 + w*16 + lr;
        const float* qbase = q + (size_t)(b*Sz)*Dm + h*HD;
        #pragma unroll
        for (int k8 = 0; k8 < 8; k8++) {
            #pragma unroll
            for (int i = 0; i < 4; i++) {
                int rr = r0 + (i & 1)*8;
                int cc = k8*8 + lc + (i >> 1)*4;
                float qv = qbase[(size_t)rr*Dm + cc];
                float qbig = tf32r(qv);
                Qb[k8][i] = __float_as_uint(qbig);
                Qs[k8][i] = __float_as_uint(tf32r(qv - qbig));
            }
        }
    }

    float m0 = -1e30f, m1 = -1e30f, l0 = 0.0f, l1 = 0.0f;
    float acc[8][4];
    #pragma unroll
    for (int nt = 0; nt < 8; nt++)
        #pragma unroll
        for (int i = 0; i < 4; i++) acc[nt][i] = 0.0f;

    int gi0 = i0 + w*16 + lr;

    for (int j0 = 0; j0 < Sz; j0 += 64) {
        __syncthreads();
        // ---- load K (split) and V tiles ----
        for (int f = tid; f < 64*16; f += 128) {
            int r = f >> 4, c4 = (f & 15) * 4;
            size_t base = (size_t)(b*Sz + j0 + r) * Dm + h*HD + c4;
            float4 kv = *(const float4*)(k + base);
            float4 kb, ks;
            kb.x = tf32r(kv.x); ks.x = tf32r(kv.x - kb.x);
            kb.y = tf32r(kv.y); ks.y = tf32r(kv.y - kb.y);
            kb.z = tf32r(kv.z); ks.z = tf32r(kv.z - kb.z);
            kb.w = tf32r(kv.w); ks.w = tf32r(kv.w - kb.w);
            *(float4*)(&sKb[r*KPAD + c4]) = kb;
            *(float4*)(&sKs[r*KPAD + c4]) = ks;
            float4 vv = *(const float4*)(v + base);
            vv.x = tf32r(vv.x); vv.y = tf32r(vv.y);
            vv.z = tf32r(vv.z); vv.w = tf32r(vv.w);
            *(float4*)(&sV[r*VPAD + c4]) = vv;
        }
        __syncthreads();

        // ---- S = Q K^T (3-mma split) ----
        float s[8][4];
        #pragma unroll
        for (int nt = 0; nt < 8; nt++)
            #pragma unroll
            for (int i = 0; i < 4; i++) s[nt][i] = 0.0f;

        #pragma unroll
        for (int k8 = 0; k8 < 8; k8++) {
            #pragma unroll
            for (int nt = 0; nt < 8; nt++) {
                int bo = (nt*8 + lr)*KPAD + k8*8 + lc;
                unsigned kb0 = __float_as_uint(sKb[bo]);
                unsigned kb1 = __float_as_uint(sKb[bo + 4]);
                unsigned ks0 = __float_as_uint(sKs[bo]);
                unsigned ks1 = __float_as_uint(sKs[bo + 4]);
                mma_tf32(s[nt], Qb[k8], kb0, kb1);
                mma_tf32(s[nt], Qs[k8], kb0, kb1);
                mma_tf32(s[nt], Qb[k8], ks0, ks1);
            }
        }

        // ---- scale + gcd bias (arith_bias is per-head constant: softmax-invariant, dropped) ----
        #pragma unroll
        for (int nt = 0; nt < 8; nt++) {
            size_t cix = (size_t)gi0*Sz + j0 + nt*8 + 2*lc;
            float2 b0 = *(const float2*)(biasB + cix);
            float2 b1 = *(const float2*)(biasB + cix + 8*(size_t)Sz);
            s[nt][0] = fmaf(b0.x, gw, s[nt][0]*scale);
            s[nt][1] = fmaf(b0.y, gw, s[nt][1]*scale);
            s[nt][2] = fmaf(b1.x, gw, s[nt][2]*scale);
            s[nt][3] = fmaf(b1.y, gw, s[nt][3]*scale);
        }

        // ---- online softmax (rows lr and lr+8; reduce over quad lanes) ----
        float tm0 = -1e30f, tm1 = -1e30f;
        #pragma unroll
        for (int nt = 0; nt < 8; nt++) {
            tm0 = fmaxf(tm0, fmaxf(s[nt][0], s[nt][1]));
            tm1 = fmaxf(tm1, fmaxf(s[nt][2], s[nt][3]));
        }
        tm0 = fmaxf(tm0, __shfl_xor_sync(0xffffffffu, tm0, 1));
        tm0 = fmaxf(tm0, __shfl_xor_sync(0xffffffffu, tm0, 2));
        tm1 = fmaxf(tm1, __shfl_xor_sync(0xffffffffu, tm1, 1));
        tm1 = fmaxf(tm1, __shfl_xor_sync(0xffffffffu, tm1, 2));
        float mn0 = fmaxf(m0, tm0), mn1 = fmaxf(m1, tm1);
        float c0 = __expf(m0 - mn0), c1 = __expf(m1 - mn1);
        float sum0 = 0.0f, sum1 = 0.0f;
        #pragma unroll
        for (int nt = 0; nt < 8; nt++) {
            s[nt][0] = __expf(s[nt][0] - mn0);
            s[nt][1] = __expf(s[nt][1] - mn0);
            s[nt][2] = __expf(s[nt][2] - mn1);
            s[nt][3] = __expf(s[nt][3] - mn1);
            sum0 += s[nt][0] + s[nt][1];
            sum1 += s[nt][2] + s[nt][3];
        }
        sum0 += __shfl_xor_sync(0xffffffffu, sum0, 1);
        sum0 += __shfl_xor_sync(0xffffffffu, sum0, 2);
        sum1 += __shfl_xor_sync(0xffffffffu, sum1, 1);
        sum1 += __shfl_xor_sync(0xffffffffu, sum1, 2);
        l0 = l0*c0 + sum0;  m0 = mn0;
        l1 = l1*c1 + sum1;  m1 = mn1;
        #pragma unroll
        for (int nt = 0; nt < 8; nt++) {
            acc[nt][0] *= c0; acc[nt][1] *= c0;
            acc[nt][2] *= c1; acc[nt][3] *= c1;
        }

        // ---- P to SMEM (warp-private region), reload as A-fragments ----
        #pragma unroll
        for (int nt = 0; nt < 8; nt++) {
            int po = (w*16 + lr)*PPAD + nt*8 + 2*lc;
            *(float2*)(&sP[po]) = make_float2(tf32r(s[nt][0]), tf32r(s[nt][1]));
            *(float2*)(&sP[po + 8*PPAD]) = make_float2(tf32r(s[nt][2]), tf32r(s[nt][3]));
        }
        __syncwarp();

        // ---- acc += P @ V ----
        #pragma unroll
        for (int k8 = 0; k8 < 8; k8++) {
            int ao = (w*16 + lr)*PPAD + k8*8 + lc;
            unsigned a[4];
            a[0] = __float_as_uint(sP[ao]);
            a[1] = __float_as_uint(sP[ao + 8*PPAD]);
            a[2] = __float_as_uint(sP[ao + 4]);
            a[3] = __float_as_uint(sP[ao + 8*PPAD + 4]);
            #pragma unroll
            for (int nt = 0; nt < 8; nt++) {
                int bo = (k8*8 + lc)*VPAD + nt*8 + lr;
                unsigned b0 = __float_as_uint(sV[bo]);
                unsigned b1 = __float_as_uint(sV[bo + 4*VPAD]);
                mma_tf32(acc[nt], a, b0, b1);
            }
        }
    }

    // ---- epilogue: normalize, round to tf32 for O-proj, write ----
    float inv0 = 1.0f / l0, inv1 = 1.0f / l1;
    #pragma unroll
    for (int nt = 0; nt < 8; nt++) {
        int col = h*HD + nt*8 + 2*lc;
        float2 o0 = make_float2(tf32r(acc[nt][0]*inv0), tf32r(acc[nt][1]*inv0));
        float2 o1 = make_float2(tf32r(acc[nt][2]*inv1), tf32r(acc[nt][3]*inv1));
        *(float2*)(o + (size_t)(b*Sz + gi0)*Dm + col) = o0;
        *(float2*)(o + (size_t)(b*Sz + gi0 + 8)*Dm + col) = o1;
    }
}

// ---------------- launch ----------------
extern "C" void kernel_launch(void* const* d_in, const int* in_sizes, int n_in,
                              void* d_out, int out_size)
{
    int enc_idx = -1;
    for (int i = 0; i < n_in; i++) if (in_sizes[i] == 4096) { enc_idx = i; break; }
    if (enc_idx < 0) enc_idx = 0;

    const float* P[24];
    int p = 0;
    for (int i = 0; i < n_in && p < 24; i++) {
        if (i == enc_idx) continue;
        P[p++] = (const float*)d_in[i];
    }
    const int* enc = (const int*)d_in[enc_idx];
    const float *q_w = P[0],  *q_b = P[1],  *k_w = P[2],  *k_b = P[3];
    const float *v_w = P[4],  *v_b = P[5],  *o_w = P[6],  *o_b = P[7];
    const float *emb1_w = P[8],  *emb1_b = P[9],  *emb2_w = P[10], *emb2_b = P[11];
    const float *log_w = P[12],  *log_b = P[13],  *prime_w = P[14], *prime_b = P[15];
    const float *div_w = P[16],  *div_b = P[17],  *bit_w = P[18],  *bit_b = P[19];
    const float *fus_w = P[20],  *fus_b = P[21],  *arith = P[22],  *gcdw = P[23];
    (void)arith;
    float* out = (float*)d_out;

    float *featA, *featF, *hidden, *Q, *K, *V, *attn, *biasM, *zb;
    cudaGetSymbolAddress((void**)&featA,  g_featA);
    cudaGetSymbolAddress((void**)&featF,  g_featF);
    cudaGetSymbolAddress((void**)&hidden, g_hidden);
    cudaGetSymbolAddress((void**)&Q,      g_q);
    cudaGetSymbolAddress((void**)&K,      g_k);
    cudaGetSymbolAddress((void**)&V,      g_v);
    cudaGetSymbolAddress((void**)&attn,   g_attn);
    cudaGetSymbolAddress((void**)&biasM,  g_bias);
    cudaGetSymbolAddress((void**)&zb,     g_zero_bias);

    cudaFuncSetAttribute(gemm_hidden_t, cudaFuncAttributeMaxDynamicSharedMemorySize, GSMEM);
    cudaFuncSetAttribute(gemm_qkv_t,    cudaFuncAttributeMaxDynamicSharedMemorySize, GSMEM);
    cudaFuncSetAttribute(gemm_single_t, cudaFuncAttributeMaxDynamicSharedMemorySize, GSMEM);
    cudaFuncSetAttribute(attention_mma_kernel, cudaFuncAttributeMaxDynamicSharedMemorySize, ATTN_SMEM);

    // Launch order matters for ncu -s 5 -c 1: attention is launch #6.
    featurize_kernel<<<NT, 256>>>(enc, emb1_w, emb1_b, log_w, log_b,
                                  prime_w, prime_b, div_w, div_b, bit_w, bit_b,
                                  featA, featF);                                      // 1
    bias_kernel<<<(Sz*Sz)/256, 256>>>(enc, biasM, 0);                                 // 2
    bias_kernel<<<(Sz*Sz)/256, 256>>>(enc, biasM, 1);                                 // 3
    gemm_hidden_t<<<dim3(8, 32), 256, GSMEM>>>(featA, emb2_w, featF, fus_w,
                                               emb2_b, fus_b, hidden);                // 4
    gemm_qkv_t<<<dim3(8, 32, 3), 256, GSMEM>>>(hidden, q_w, q_b, k_w, k_b, v_w, v_b,
                                               zb, Q, K, V);                          // 5
    attention_mma_kernel<<<dim3(Sz/64, Bz*Hh), 128, ATTN_SMEM>>>(Q, K, V, biasM,
                                                                 gcdw, attn);         // 6
    gemm_single_t<<<dim3(8, 32), 256, GSMEM>>>(attn, o_w, o_b, zb, out);              // 7
}